// round 4
// baseline (speedup 1.0000x reference)
#include <cuda_runtime.h>
#include <cstdint>

#define N_BOX     8192
#define MAX_KEEP  256
#define MIN_SCORE 0.3f
#define NMS_THR   0.3f
#define NT        1024
#define NBKT      4096
#define BATCH     128
#define FULL      0xFFFFFFFFu

extern __shared__ unsigned char dynsmem[];

__global__ void __launch_bounds__(NT, 1)
detect_kernel(const float* __restrict__ score,
              const float* __restrict__ box,
              float* __restrict__ out)
{
    // ---- dynamic smem layout (224 KB) ----
    // [0,128K)      s_cbox : sorted candidate bbox xyxy (float4)       [phase 1.5 + 2]
    // [128K,192K)   s_key  : sorted u64 keys (~score_bits, idx)        [phase 1 + 2]
    // [192K,224K)   overlay:
    //    phase 1:  s_cnt (16K) + s_off (16K)
    //    phase 2:  s_dead(8K) s_kbox(4K) s_kar(1K) s_ksc(1K) s_kid(1K) s_cb(2K) s_rowm(2K)
    float4*             s_cbox = (float4*)dynsmem;
    unsigned long long* s_key  = (unsigned long long*)(dynsmem + 131072);
    unsigned int*       s_cnt  = (unsigned int*)(dynsmem + 196608);
    unsigned int*       s_off  = (unsigned int*)(dynsmem + 212992);
    unsigned char*      s_dead = (unsigned char*)(dynsmem + 196608);
    float4*             s_kbox = (float4*)(dynsmem + 204800);
    float*              s_kar  = (float*) (dynsmem + 208896);
    float*              s_ksc  = (float*) (dynsmem + 209920);
    int*                s_kid  = (int*)   (dynsmem + 210944);
    float4*             s_cb   = (float4*)(dynsmem + 211968);
    unsigned int*       s_rowm = (unsigned int*)(dynsmem + 214016);

    __shared__ unsigned int s_wsum[32];
    __shared__ int s_nvalid, s_kc;

    const int tid  = threadIdx.x;
    const int lane = tid & 31;
    const int wid  = tid >> 5;

    // ================= phase 1: bucket sort (exact stable descending) =================
    for (int i = tid; i < NBKT; i += NT) s_cnt[i] = 0;
    __syncthreads();

    float sc[8]; int bk[8];
    #pragma unroll
    for (int k = 0; k < 8; k++) {
        int i = tid + k * NT;
        float s = score[i];
        sc[k] = s;
        int b = -1;
        if (s >= MIN_SCORE) {
            b = 4095 - min(4095, (int)(s * 4096.0f));   // score desc -> bucket asc (monotone)
            atomicAdd(&s_cnt[b], 1u);
        }
        bk[k] = b;
    }
    __syncthreads();

    // exclusive scan of 4096 counters
    unsigned int c0 = s_cnt[tid*4+0], c1 = s_cnt[tid*4+1], c2 = s_cnt[tid*4+2], c3 = s_cnt[tid*4+3];
    unsigned int tsum = c0 + c1 + c2 + c3;
    unsigned int p = tsum;
    #pragma unroll
    for (int d = 1; d < 32; d <<= 1) {
        unsigned int v = __shfl_up_sync(FULL, p, d);
        if (lane >= d) p += v;
    }
    if (lane == 31) s_wsum[wid] = p;
    __syncthreads();
    if (wid == 0) {
        unsigned int w = s_wsum[lane];
        unsigned int q = w;
        #pragma unroll
        for (int d = 1; d < 32; d <<= 1) {
            unsigned int v = __shfl_up_sync(FULL, q, d);
            if (lane >= d) q += v;
        }
        s_wsum[lane] = q - w;
        if (lane == 31) s_nvalid = (int)q;
    }
    __syncthreads();
    unsigned int base = s_wsum[wid] + (p - tsum);
    s_off[tid*4+0] = base;
    s_off[tid*4+1] = base + c0;
    s_off[tid*4+2] = base + c0 + c1;
    s_off[tid*4+3] = base + c0 + c1 + c2;
    __syncthreads();

    // scatter (afterwards s_off[b] = start of bucket b+1)
    #pragma unroll
    for (int k = 0; k < 8; k++) {
        if (bk[k] >= 0) {
            int i = tid + k * NT;
            unsigned int pos = atomicAdd(&s_off[bk[k]], 1u);
            s_key[pos] = ((unsigned long long)(~__float_as_uint(sc[k])) << 32) | (unsigned int)i;
        }
    }
    __syncthreads();

    // intra-bucket insertion sort on full u64 key (exact total order)
    for (int b = tid; b < NBKT; b += NT) {
        int lo = b ? (int)s_off[b-1] : 0;
        int hi = (int)s_off[b];
        for (int i = lo + 1; i < hi; i++) {
            unsigned long long v = s_key[i];
            int j = i - 1;
            while (j >= lo && s_key[j] > v) { s_key[j+1] = s_key[j]; j--; }
            s_key[j+1] = v;
        }
    }
    __syncthreads();           // sort done; s_cnt/s_off dead from here

    const int nval = s_nvalid;

    // ============ phase 1.5: pre-gather candidate boxes (xyxy) + init dead flags ============
    for (int c = tid; c < nval; c += NT) {
        int idx = (int)(s_key[c] & 0xFFFFFFFFull);
        float4 b4 = *(const float4*)(box + idx * 16);
        float hw = b4.z * 0.5f, hh = b4.w * 0.5f;
        s_cbox[c] = make_float4(b4.x - hw, b4.y - hh, b4.x + hw, b4.y + hh);
    }
    for (int c = tid; c < N_BOX; c += NT) s_dead[c] = 0;
    __syncthreads();

    // ================= phase 2: batched greedy NMS (128-wide) =================
    int kc = 0;
    for (int cb = 0; cb < nval && kc < MAX_KEEP; cb += BATCH) {
        // ---- stage 128 candidates ----
        if (tid < BATCH) {
            int c = cb + tid;
            if (c < nval) s_cb[tid] = s_cbox[c];
        }
        __syncthreads();

        // ---- intra-batch IoU rows: warp wid computes rows 4*wid..4*wid+3 ----
        const int nb = min(BATCH, nval - cb);
        #pragma unroll
        for (int rr = 0; rr < 4; rr++) {
            int r = (wid << 2) | rr;
            if (r < nb) {
                float4 B  = s_cb[r];
                float  AR = (B.z - B.x) * (B.w - B.y);
                unsigned int w0 = 0, w1 = 0, w2 = 0, w3 = 0;
                #pragma unroll
                for (int j = 0; j < 4; j++) {
                    int cc = (j << 5) | lane;
                    float4 b = s_cb[cc];
                    float lx = fmaxf(B.x, b.x), ly = fmaxf(B.y, b.y);
                    float rx = fminf(B.z, b.z), ry = fminf(B.w, b.w);
                    float iw = fmaxf(rx - lx, 0.0f), ih = fmaxf(ry - ly, 0.0f);
                    float inter = iw * ih;
                    float arb = (b.z - b.x) * (b.w - b.y);
                    bool hit = inter / (AR + arb - inter + 1e-9f) > NMS_THR;
                    unsigned int bal = __ballot_sync(FULL, hit);
                    if (j == 0) w0 = bal; else if (j == 1) w1 = bal;
                    else if (j == 2) w2 = bal; else w3 = bal;
                }
                if (lane == 0) {
                    s_rowm[(r<<2)+0] = w0; s_rowm[(r<<2)+1] = w1;
                    s_rowm[(r<<2)+2] = w2; s_rowm[(r<<2)+3] = w3;
                }
            }
        }
        __syncthreads();

        // ---- warp 0: cooperative greedy resolve (lane L owns candidates 4L..4L+3) ----
        if (wid == 0) {
            int c0 = cb + (lane << 2);
            unsigned int d = *(const unsigned int*)(s_dead + c0);
            unsigned int a4 = 0;
            #pragma unroll
            for (int i = 0; i < 4; i++)
                if ((c0 + i) < nval && ((d >> (8 * i)) & 1u) == 0u) a4 |= (1u << i);

            int kcl = kc;
            while (true) {
                int myf = a4 ? ((lane << 2) + __ffs(a4) - 1) : (1 << 30);
                int t = __reduce_min_sync(FULL, myf);
                if (t >= BATCH || kcl >= MAX_KEEP) break;
                if (lane == (t >> 2)) {
                    float4 bb = s_cb[t];
                    s_kbox[kcl] = bb;
                    s_kar[kcl]  = (bb.z - bb.x) * (bb.w - bb.y);
                    unsigned long long key = s_key[cb + t];
                    s_kid[kcl] = (int)(key & 0xFFFFFFFFull);
                    s_ksc[kcl] = __uint_as_float(~(unsigned int)(key >> 32));
                    a4 &= ~(1u << (t & 3));      // retire even if degenerate self-IoU
                }
                kcl++;
                unsigned int w = s_rowm[(t << 2) + (lane >> 3)];
                a4 &= ~((w >> ((lane & 7) << 2)) & 0xFu);
            }
            if (lane == 0) s_kc = kcl;
        }
        __syncthreads();

        int kc0 = kc;
        kc = s_kc;

        // ---- propagate new kept to remaining candidates (incremental dead flags) ----
        if (kc > kc0 && kc < MAX_KEEP) {
            for (int pp = cb + BATCH + tid; pp < nval; pp += NT) {
                if (s_dead[pp]) continue;
                float4 b = s_cbox[pp];
                float arb = (b.z - b.x) * (b.w - b.y);
                for (int k = kc0; k < kc; k++) {
                    float4 B = s_kbox[k];
                    float lx = fmaxf(B.x, b.x), ly = fmaxf(B.y, b.y);
                    float rx = fminf(B.z, b.z), ry = fminf(B.w, b.w);
                    float iw = fmaxf(rx - lx, 0.0f), ih = fmaxf(ry - ly, 0.0f);
                    float inter = iw * ih;
                    if (inter / (s_kar[k] + arb - inter + 1e-9f) > NMS_THR) {
                        s_dead[pp] = 1;
                        break;
                    }
                }
            }
        }
        __syncthreads();
    }

    // ================= outputs =================
    // layout: [0,256) score | [256,4352) box (256x16) | [4352,4608) valid
    for (int k = tid; k < MAX_KEEP; k += NT) {
        bool v = k < kc;
        out[k]        = v ? s_ksc[k] : 0.0f;
        out[4352 + k] = v ? 1.0f : 0.0f;
    }
    for (int e = tid; e < MAX_KEEP * 16; e += NT) {
        int k = e >> 4, c = e & 15;
        out[256 + e] = (k < kc) ? box[s_kid[k] * 16 + c] : 0.0f;
    }
}

// ---------------- launch ----------------
extern "C" void kernel_launch(void* const* d_in, const int* in_sizes, int n_in,
                              void* d_out, int out_size) {
    const float* score = (const float*)d_in[0];
    const float* box   = (const float*)d_in[1];
    float* out = (float*)d_out;

    const int dyn = 229376;   // 224 KB
    cudaFuncSetAttribute(detect_kernel,
                         cudaFuncAttributeMaxDynamicSharedMemorySize, dyn);
    detect_kernel<<<1, NT, dyn>>>(score, box, out);
}

// round 5
// speedup vs baseline: 3.5282x; 3.5282x over previous
#include <cuda_runtime.h>
#include <cstdint>

#define N_BOX     8192
#define MAX_KEEP  256
#define MIN_SCORE 0.3f
#define NMS_THR   0.3f
#define NT        1024
#define NBKT      4096
#define BATCH     64
#define FULL      0xFFFFFFFFu

extern __shared__ unsigned char dynsmem[];

__global__ void __launch_bounds__(NT, 1)
detect_kernel(const float* __restrict__ score,
              const float* __restrict__ box,
              float* __restrict__ out)
{
    // ---- dynamic smem (192 KB) ----
    // [0,128K)    s_cbox : sorted candidate bbox xyxy (float4)  [written phase 1.5]
    //             phase-1 overlay: s_cnt [0,16K) + s_off [16K,32K)
    // [128K,192K) s_key  : sorted u64 keys (~score_bits, idx)
    float4*             s_cbox = (float4*)dynsmem;
    unsigned long long* s_key  = (unsigned long long*)(dynsmem + 131072);
    unsigned int*       s_cnt  = (unsigned int*)dynsmem;
    unsigned int*       s_off  = (unsigned int*)(dynsmem + 16384);

    __shared__ float4 s_kbox[MAX_KEEP];
    __shared__ float  s_kar[MAX_KEEP];
    __shared__ float  s_ksc[MAX_KEEP];
    __shared__ int    s_kid[MAX_KEEP];
    __shared__ unsigned long long s_row[BATCH];
    __shared__ unsigned char s_sup[BATCH];
    __shared__ unsigned int s_wsum[32];
    __shared__ int s_nvalid, s_kc;

    const int tid  = threadIdx.x;
    const int lane = tid & 31;
    const int wid  = tid >> 5;

    // ================= phase 1: bucket sort (exact stable descending) =================
    for (int i = tid; i < NBKT; i += NT) s_cnt[i] = 0;
    if (tid == 0) s_kc = 0;
    __syncthreads();

    float sc[8]; int bk[8];
    #pragma unroll
    for (int k = 0; k < 8; k++) {
        int i = tid + k * NT;
        float s = score[i];
        sc[k] = s;
        int b = -1;
        if (s >= MIN_SCORE) {
            b = 4095 - min(4095, (int)(s * 4096.0f));   // score desc -> bucket asc (monotone)
            atomicAdd(&s_cnt[b], 1u);
        }
        bk[k] = b;
    }
    __syncthreads();

    // exclusive scan of 4096 counters
    unsigned int c0 = s_cnt[tid*4+0], c1 = s_cnt[tid*4+1], c2 = s_cnt[tid*4+2], c3 = s_cnt[tid*4+3];
    unsigned int tsum = c0 + c1 + c2 + c3;
    unsigned int p = tsum;
    #pragma unroll
    for (int d = 1; d < 32; d <<= 1) {
        unsigned int v = __shfl_up_sync(FULL, p, d);
        if (lane >= d) p += v;
    }
    if (lane == 31) s_wsum[wid] = p;
    __syncthreads();
    if (wid == 0) {
        unsigned int w = s_wsum[lane];
        unsigned int q = w;
        #pragma unroll
        for (int d = 1; d < 32; d <<= 1) {
            unsigned int v = __shfl_up_sync(FULL, q, d);
            if (lane >= d) q += v;
        }
        s_wsum[lane] = q - w;
        if (lane == 31) s_nvalid = (int)q;
    }
    __syncthreads();
    unsigned int basep = s_wsum[wid] + (p - tsum);
    s_off[tid*4+0] = basep;
    s_off[tid*4+1] = basep + c0;
    s_off[tid*4+2] = basep + c0 + c1;
    s_off[tid*4+3] = basep + c0 + c1 + c2;
    __syncthreads();

    // scatter (afterwards s_off[b] = start of bucket b+1)
    #pragma unroll
    for (int k = 0; k < 8; k++) {
        if (bk[k] >= 0) {
            int i = tid + k * NT;
            unsigned int pos = atomicAdd(&s_off[bk[k]], 1u);
            s_key[pos] = ((unsigned long long)(~__float_as_uint(sc[k])) << 32) | (unsigned int)i;
        }
    }
    __syncthreads();

    // intra-bucket insertion sort on full u64 key (exact total order)
    for (int b = tid; b < NBKT; b += NT) {
        int lo = b ? (int)s_off[b-1] : 0;
        int hi = (int)s_off[b];
        for (int i = lo + 1; i < hi; i++) {
            unsigned long long v = s_key[i];
            int j = i - 1;
            while (j >= lo && s_key[j] > v) { s_key[j+1] = s_key[j]; j--; }
            s_key[j+1] = v;
        }
    }
    __syncthreads();               // sort done; cnt/off regions dead from here

    const int nval = s_nvalid;

    // ========== phase 1.5: pre-gather candidate boxes (xyxy) into smem ==========
    for (int c = tid; c < nval; c += NT) {
        int idx = (int)(s_key[c] & 0xFFFFFFFFull);
        float4 b4 = *(const float4*)(box + idx * 16);
        float hw = b4.z * 0.5f, hh = b4.w * 0.5f;
        s_cbox[c] = make_float4(b4.x - hw, b4.y - hh, b4.x + hw, b4.y + hh);
    }
    __syncthreads();

    // ================= phase 2: batched greedy NMS (64-wide, 2 barriers/batch) =================
    int kc = 0;
    for (int cb = 0; cb < nval && kc < MAX_KEEP; cb += BATCH) {
        const int nb = min(BATCH, nval - cb);

        // lane-owned candidate boxes for ballot groups (g0: c=lane, g1: c=32+lane)
        float4 cbx0 = s_cbox[cb + lane];                       // may be garbage if >= nb (guarded)
        float4 cbx1 = (32 + lane < nb) ? s_cbox[cb + 32 + lane] : make_float4(0,0,0,0);
        float ar0 = (cbx0.z - cbx0.x) * (cbx0.w - cbx0.y);
        float ar1 = (cbx1.z - cbx1.x) * (cbx1.w - cbx1.y);

        // warp wid owns candidates r0=2*wid, r1=2*wid+1
        #pragma unroll
        for (int rr = 0; rr < 2; rr++) {
            int r = (wid << 1) | rr;
            if (r < nb) {
                float4 B  = s_cbox[cb + r];
                float  AR = (B.z - B.x) * (B.w - B.y);

                // intra-batch row (64 bits via 2 ballots)
                float lx = fmaxf(B.x, cbx0.x), ly = fmaxf(B.y, cbx0.y);
                float rx = fminf(B.z, cbx0.z), ry = fminf(B.w, cbx0.w);
                float inter = fmaxf(rx - lx, 0.0f) * fmaxf(ry - ly, 0.0f);
                bool hit0 = (lane < nb) && (inter / (AR + ar0 - inter + 1e-9f) > NMS_THR);

                lx = fmaxf(B.x, cbx1.x); ly = fmaxf(B.y, cbx1.y);
                rx = fminf(B.z, cbx1.z); ry = fminf(B.w, cbx1.w);
                inter = fmaxf(rx - lx, 0.0f) * fmaxf(ry - ly, 0.0f);
                bool hit1 = (32 + lane < nb) && (inter / (AR + ar1 - inter + 1e-9f) > NMS_THR);

                unsigned int m0 = __ballot_sync(FULL, hit0);
                unsigned int m1 = __ballot_sync(FULL, hit1);
                if (lane == 0)
                    s_row[r] = (unsigned long long)m0 | ((unsigned long long)m1 << 32);

                // suppressed-by-kept check (32 kept at a time, ballot early-exit)
                bool sup = false;
                if (kc > 0) {
                    for (int kb = lane; ; kb += 32) {
                        bool h = false;
                        if (kb < kc) {
                            float4 K = s_kbox[kb];
                            float klx = fmaxf(B.x, K.x), kly = fmaxf(B.y, K.y);
                            float krx = fminf(B.z, K.z), kry = fminf(B.w, K.w);
                            float ki = fmaxf(krx - klx, 0.0f) * fmaxf(kry - kly, 0.0f);
                            h = ki / (AR + s_kar[kb] - ki + 1e-9f) > NMS_THR;
                        }
                        if (__ballot_sync(FULL, h)) { sup = true; break; }
                        if (kb - lane + 32 >= kc) break;
                    }
                }
                if (lane == 0) s_sup[r] = (unsigned char)sup;
            }
        }
        __syncthreads();

        // warp 0: pack sup flags via ballots, lane 0 serial greedy resolve
        if (wid == 0) {
            bool sA = (lane < nb)      ? (s_sup[lane] != 0)      : true;
            bool sB = (32 + lane < nb) ? (s_sup[32 + lane] != 0) : true;
            unsigned int mA = __ballot_sync(FULL, sA);
            unsigned int mB = __ballot_sync(FULL, sB);
            if (lane == 0) {
                unsigned long long dead = (unsigned long long)mA | ((unsigned long long)mB << 32);
                unsigned long long alivebits = (nb == 64) ? ~0ull : ((1ull << nb) - 1ull);
                unsigned long long alive = alivebits & ~dead;
                int kcl = kc;
                while (alive && kcl < MAX_KEEP) {
                    int t = __ffsll((long long)alive) - 1;
                    float4 bb = s_cbox[cb + t];
                    s_kbox[kcl] = bb;
                    s_kar[kcl]  = (bb.z - bb.x) * (bb.w - bb.y);
                    unsigned long long key = s_key[cb + t];
                    s_kid[kcl] = (int)(key & 0xFFFFFFFFull);
                    s_ksc[kcl] = __uint_as_float(~(unsigned int)(key >> 32));
                    kcl++;
                    alive &= ~s_row[t];
                    alive &= ~(1ull << t);     // retire even if degenerate self-IoU
                }
                s_kc = kcl;
            }
        }
        __syncthreads();
        kc = s_kc;
    }

    // ================= outputs =================
    // layout: [0,256) score | [256,4352) box (256x16) | [4352,4608) valid
    for (int k = tid; k < MAX_KEEP; k += NT) {
        bool v = k < kc;
        out[k]        = v ? s_ksc[k] : 0.0f;
        out[4352 + k] = v ? 1.0f : 0.0f;
    }
    for (int e = tid; e < MAX_KEEP * 16; e += NT) {
        int k = e >> 4, c = e & 15;
        out[256 + e] = (k < kc) ? box[s_kid[k] * 16 + c] : 0.0f;
    }
}

// ---------------- launch ----------------
extern "C" void kernel_launch(void* const* d_in, const int* in_sizes, int n_in,
                              void* d_out, int out_size) {
    const float* score = (const float*)d_in[0];
    const float* box   = (const float*)d_in[1];
    float* out = (float*)d_out;

    const int dyn = 196608;   // 192 KB
    cudaFuncSetAttribute(detect_kernel,
                         cudaFuncAttributeMaxDynamicSharedMemorySize, dyn);
    detect_kernel<<<1, NT, dyn>>>(score, box, out);
}